// round 10
// baseline (speedup 1.0000x reference)
#include <cuda_runtime.h>
#include <cuda_bf16.h>
#include <cuda_fp16.h>
#include <cstdint>

#define DDIM 50
#define MAXK 2048
#define TM   128      // rows per CTA (16 rows per warp, 8 warps)
#define TKT  64       // K-slots per tile

// ---------------- static device scratch (pre-split M) ------------------------
__device__ __align__(16) __nv_bfloat16 gMkA[MAXK * 64];   // [slot][d] hi (GEMM1)
__device__ __align__(16) __nv_bfloat16 gMkB[MAXK * 64];   // [slot][d] lo (GEMM1)
__device__ __align__(16) __half       gMdF[64 * MAXK];    // [d][slot] fp16 (GEMM2)
__device__ __align__(16) float        gMt[MAXK * 2];      // [slot][2]: m48, m49 fp32

// ---------------- smem layout (bytes) ----------------------------------------
#define ARR      9216                    // 64 rows * 144B pitch
#define SM_KH    0
#define SM_KL    ARR
#define SM_DF    (2 * ARR)
#define SM_TAIL  (3 * ARR)               // 27648
#define SM_TOTAL (SM_TAIL + 512)         // 28160

// ---------------- helpers ----------------------------------------------------
__device__ __forceinline__ uint32_t smem_u32(const void* p) {
    uint32_t a;
    asm("{ .reg .u64 t; cvta.to.shared.u64 t, %1; cvt.u32.u64 %0, t; }" : "=r"(a) : "l"(p));
    return a;
}
__device__ __forceinline__ float4 lds128f(uint32_t addr) {
    float4 v;
    asm("ld.shared.v4.f32 {%0, %1, %2, %3}, [%4];"
        : "=f"(v.x), "=f"(v.y), "=f"(v.z), "=f"(v.w) : "r"(addr));
    return v;
}
__device__ __forceinline__ void ldm4(uint32_t* r, uint32_t addr) {
    asm volatile("ldmatrix.sync.aligned.m8n8.x4.shared.b16 {%0,%1,%2,%3}, [%4];"
                 : "=r"(r[0]), "=r"(r[1]), "=r"(r[2]), "=r"(r[3]) : "r"(addr));
}
__device__ __forceinline__ void ldm2(uint32_t* r, uint32_t addr) {
    asm volatile("ldmatrix.sync.aligned.m8n8.x2.shared.b16 {%0,%1}, [%2];"
                 : "=r"(r[0]), "=r"(r[1]) : "r"(addr));
}
__device__ __forceinline__ uint32_t pack2(float lo, float hi) {   // -> bf16x2
    uint32_t r;
    asm("{ .reg .b16 l, h; cvt.rn.bf16.f32 l, %1; cvt.rn.bf16.f32 h, %2; mov.b32 %0, {l, h}; }"
        : "=r"(r) : "f"(lo), "f"(hi));
    return r;
}
__device__ __forceinline__ uint32_t packh2(float lo, float hi) {  // -> f16x2
    uint32_t r;
    asm("{ .reg .b16 l, h; cvt.rn.f16.f32 l, %1; cvt.rn.f16.f32 h, %2; mov.b32 %0, {l, h}; }"
        : "=r"(r) : "f"(lo), "f"(hi));
    return r;
}
__device__ __forceinline__ float bf16_rt(float v) {               // round-trip
    float r;
    asm("{ .reg .b16 t; cvt.rn.bf16.f32 t, %1; cvt.f32.bf16 %0, t; }" : "=f"(r) : "f"(v));
    return r;
}
// D += A * B   (m16n8k16, row.col, bf16 in, f32 accum)
__device__ __forceinline__ void mma(float* d, const uint32_t* a, uint32_t b0, uint32_t b1) {
    asm volatile(
        "mma.sync.aligned.m16n8k16.row.col.f32.bf16.bf16.f32 "
        "{%0,%1,%2,%3}, {%4,%5,%6,%7}, {%8,%9}, {%0,%1,%2,%3};"
        : "+f"(d[0]), "+f"(d[1]), "+f"(d[2]), "+f"(d[3])
        : "r"(a[0]), "r"(a[1]), "r"(a[2]), "r"(a[3]), "r"(b0), "r"(b1));
}
// D += A * B   (m16n8k16, row.col, fp16 in, f32 accum)
__device__ __forceinline__ void mmah(float* d, const uint32_t* a, uint32_t b0, uint32_t b1) {
    asm volatile(
        "mma.sync.aligned.m16n8k16.row.col.f32.f16.f16.f32 "
        "{%0,%1,%2,%3}, {%4,%5,%6,%7}, {%8,%9}, {%0,%1,%2,%3};"
        : "+f"(d[0]), "+f"(d[1]), "+f"(d[2]), "+f"(d[3])
        : "r"(a[0]), "r"(a[1]), "r"(a[2]), "r"(a[3]), "r"(b0), "r"(b1));
}
__device__ __forceinline__ float qmax(float v) {   // max across the tg-quad
    v = fmaxf(v, __shfl_xor_sync(0xffffffffu, v, 1));
    v = fmaxf(v, __shfl_xor_sync(0xffffffffu, v, 2));
    return v;
}
#define CP16(dst, src) asm volatile("cp.async.cg.shared.global [%0], [%1], 16;" :: "r"(dst), "l"(src))
#define CPCOMMIT()     asm volatile("cp.async.commit_group;" ::: "memory")
#define CPWAIT0()      asm volatile("cp.async.wait_group 0;" ::: "memory")

// ---------------- prep: M splits + fp16 D-major + fp32 tail -------------------
__global__ void prep_kernel(const float* __restrict__ mem, int K) {
    int i = blockIdx.x * blockDim.x + threadIdx.x;
    if (i >= MAXK * 64) return;
    int k = i >> 6, d = i & 63;
    float v = (d < DDIM && k < K) ? mem[k * DDIM + d] : 0.f;
    float h = bf16_rt(v);
    gMkA[k * 64 + d] = __float2bfloat16(h);
    gMkB[k * 64 + d] = __float2bfloat16(v - h);
    gMdF[d * MAXK + k] = __float2half(v);
    if (d < 2) gMt[k * 2 + d] = (k < K) ? mem[k * DDIM + 48 + d] : 0.f;
}

// ---------------- main fused kernel ------------------------------------------
__global__ __launch_bounds__(256, 2)
void memread_mma_kernel(const float* __restrict__ x, float* __restrict__ out, int B, int K) {
    extern __shared__ char smem[];
    const uint32_t sb = smem_u32(smem);
    const int tid = threadIdx.x, wid = tid >> 5, lane = tid & 31;
    const int g = lane >> 2, tg = lane & 3;
    const int row0 = blockIdx.x * TM;
    const int rA = row0 + wid * 16 + g;
    const int rB = rA + 8;

    // per-lane ldmatrix row-address offset
    const uint32_t offm = (uint32_t)((lane & 7) * 144 + ((lane >> 3) & 1) * 16
                                     + ((lane >> 4) & 1) * 1152);

    // ---- prologue A: passthrough x -> out[:, 0:50] --------------------------
    for (int w = tid; w < TM * 32; w += 256) {
        int r = w >> 5, dp = w & 31;
        int row = row0 + r;
        if (dp < 25 && row < B) {
            float2 v = *reinterpret_cast<const float2*>(x + (size_t)row * DDIM + dp * 2);
            *reinterpret_cast<float2*>(out + (size_t)row * 100 + dp * 2) = v;
        }
    }

    // ---- prologue B: X A-fragments (dims 0..47) held in registers -----------
    uint32_t Xh[3][4], Xl[3][4];
    #pragma unroll
    for (int ks = 0; ks < 3; ++ks) {
        const int c0 = ks * 16 + 2 * tg;
        const int c1 = c0 + 8;
        float2 z = make_float2(0.f, 0.f);
        float2 vA0 = (rA < B) ? *reinterpret_cast<const float2*>(x + (size_t)rA * DDIM + c0) : z;
        float2 vB0 = (rB < B) ? *reinterpret_cast<const float2*>(x + (size_t)rB * DDIM + c0) : z;
        float2 vA1 = (rA < B) ? *reinterpret_cast<const float2*>(x + (size_t)rA * DDIM + c1) : z;
        float2 vB1 = (rB < B) ? *reinterpret_cast<const float2*>(x + (size_t)rB * DDIM + c1) : z;
        float hA0x = bf16_rt(vA0.x), hA0y = bf16_rt(vA0.y);
        float hB0x = bf16_rt(vB0.x), hB0y = bf16_rt(vB0.y);
        float hA1x = bf16_rt(vA1.x), hA1y = bf16_rt(vA1.y);
        float hB1x = bf16_rt(vB1.x), hB1y = bf16_rt(vB1.y);
        Xh[ks][0] = pack2(hA0x, hA0y);
        Xh[ks][1] = pack2(hB0x, hB0y);
        Xh[ks][2] = pack2(hA1x, hA1y);
        Xh[ks][3] = pack2(hB1x, hB1y);
        Xl[ks][0] = pack2(vA0.x - hA0x, vA0.y - hA0y);
        Xl[ks][1] = pack2(vB0.x - hB0x, vB0.y - hB0y);
        Xl[ks][2] = pack2(vA1.x - hA1x, vA1.y - hA1y);
        Xl[ks][3] = pack2(vB1.x - hB1x, vB1.y - hB1y);
    }
    // fp32 x tail (dims 48,49) for rows rA, rB
    float xA48 = 0.f, xA49 = 0.f, xB48 = 0.f, xB49 = 0.f;
    if (rA < B) { float2 v = *reinterpret_cast<const float2*>(x + (size_t)rA * DDIM + 48); xA48 = v.x; xA49 = v.y; }
    if (rB < B) { float2 v = *reinterpret_cast<const float2*>(x + (size_t)rB * DDIM + 48); xB48 = v.x; xB49 = v.y; }

    float U[7][4];
    #pragma unroll
    for (int nb = 0; nb < 7; ++nb)
        #pragma unroll
        for (int q = 0; q < 4; ++q) U[nb][q] = 0.f;

    float mA = -1e30f, mB = -1e30f;      // flash-style running row maxes

    const uint32_t KH = sb + SM_KH, KL = sb + SM_KL, DF = sb + SM_DF;
    const uint32_t TAIL = sb + SM_TAIL;
    const int ntiles = (K + TKT - 1) / TKT;

    for (int t = 0; t < ntiles; ++t) {
        // ---- load tile t ----------------------------------------------------
        #pragma unroll
        for (int c = tid; c < 512; c += 256) {
            int r = c >> 3, j = c & 7;
            uint32_t doff = (uint32_t)(r * 144 + j * 16);
            const char* sKA = (const char*)(gMkA + (size_t)(t * TKT + r) * 64) + j * 16;
            const char* sKB = (const char*)(gMkB + (size_t)(t * TKT + r) * 64) + j * 16;
            const char* sDF = (const char*)(gMdF + (size_t)r * MAXK + t * TKT) + j * 16;
            CP16(KH + doff, sKA);
            CP16(KL + doff, sKB);
            CP16(DF + doff, sDF);
        }
        if (tid < 32)   // fp32 tail: 64 slots x (m48, m49) = 512B
            CP16(TAIL + (uint32_t)tid * 16, (const char*)(gMt + (size_t)t * 128) + tid * 16);
        CPCOMMIT();
        CPWAIT0();
        __syncthreads();

        // ---- 4 substeps -----------------------------------------------------
        #pragma unroll 1
        for (int s = 0; s < 4; ++s) {
            // GEMM1: 3 ks, 2 n-octets, error-compensated (hi*hi + hi*lo + lo*hi)
            float a0[4] = {0,0,0,0}, a1[4] = {0,0,0,0};
            float b0[4] = {0,0,0,0}, b1[4] = {0,0,0,0};
            const uint32_t kb = (uint32_t)(s * 2304) + offm;
            #pragma unroll
            for (int ks = 0; ks < 3; ++ks) {
                uint32_t bh[4], bl[4];
                ldm4(bh, KH + kb + ks * 32);
                ldm4(bl, KL + kb + ks * 32);
                mma(a0, Xh[ks], bh[0], bh[1]);
                mma(a1, Xh[ks], bh[2], bh[3]);
                mma(b0, Xh[ks], bl[0], bl[1]);
                mma(b1, Xh[ks], bl[2], bl[3]);
                mma(b0, Xl[ks], bh[0], bh[1]);
                mma(b1, Xl[ks], bh[2], bh[3]);
            }
            float S[8];
            #pragma unroll
            for (int q = 0; q < 4; ++q) {
                S[q]     = a0[q] + b0[q];
                S[4 + q] = a1[q] + b1[q];
            }

            // exact fp32 fixup for dims 48,49 (2 contiguous LDS.128)
            {
                uint32_t ta = TAIL + (uint32_t)(s * 128 + tg * 16);
                float4 t0 = lds128f(ta);        // slots 2tg, 2tg+1 (nb0)
                float4 t1 = lds128f(ta + 64);   // slots +8      (nb1)
                S[0] += xA48 * t0.x + xA49 * t0.y;
                S[1] += xA48 * t0.z + xA49 * t0.w;
                S[2] += xB48 * t0.x + xB49 * t0.y;
                S[3] += xB48 * t0.z + xB49 * t0.w;
                S[4] += xA48 * t1.x + xA49 * t1.y;
                S[5] += xA48 * t1.z + xA49 * t1.w;
                S[6] += xB48 * t1.x + xB49 * t1.y;
                S[7] += xB48 * t1.z + xB49 * t1.w;
            }

            // row maxes for this substep
            float sA = qmax(fmaxf(fmaxf(S[0], S[1]), fmaxf(S[4], S[5])));
            float sB = qmax(fmaxf(fmaxf(S[2], S[3]), fmaxf(S[6], S[7])));

            bool up = (sA > mA) | (sB > mB);
            if (__any_sync(0xffffffffu, up)) {        // rare after early tiles
                float nA = fmaxf(mA, sA), nB = fmaxf(mB, sB);
                float cA = __expf(mA - nA), cB = __expf(mB - nB);
                #pragma unroll
                for (int nb = 0; nb < 7; ++nb) {
                    U[nb][0] *= cA; U[nb][1] *= cA;
                    U[nb][2] *= cB; U[nb][3] *= cB;
                }
                mA = nA; mB = nB;
            }

            // s' = exp(S - m_row) in fp16
            uint32_t ah[4];
            ah[0] = packh2(__expf(S[0] - mA), __expf(S[1] - mA));
            ah[1] = packh2(__expf(S[2] - mB), __expf(S[3] - mB));
            ah[2] = packh2(__expf(S[4] - mA), __expf(S[5] - mA));
            ah[3] = packh2(__expf(S[6] - mB), __expf(S[7] - mB));

            // GEMM2: fp16 single pass, U[16 x 56] += s' * Md
            const uint32_t db = (uint32_t)(s * 32) + offm;
            #pragma unroll
            for (int i = 0; i < 3; ++i) {
                uint32_t dh[4];
                ldm4(dh, DF + (uint32_t)(i * 2304) + db);
                mmah(U[2 * i],     ah, dh[0], dh[1]);
                mmah(U[2 * i + 1], ah, dh[2], dh[3]);
            }
            {   // nb = 6 (d 48..55; 50..55 zero-padded)
                uint32_t d2[2];
                ldm2(d2, DF + 6 * 1152 + db);
                mmah(U[6], ah, d2[0], d2[1]);
            }
        }
        __syncthreads();                  // done with tile buffer
    }

    // ---- writeout U * e^m -> out[:, 50:100] ---------------------------------
    const float eA = __expf(mA), eB = __expf(mB);
    #pragma unroll
    for (int nb = 0; nb < 7; ++nb) {
        int col = nb * 8 + tg * 2;
        if (col < DDIM) {
            if (rA < B)
                *reinterpret_cast<float2*>(out + (size_t)rA * 100 + 50 + col) =
                    make_float2(U[nb][0] * eA, U[nb][1] * eA);
            if (rB < B)
                *reinterpret_cast<float2*>(out + (size_t)rB * 100 + 50 + col) =
                    make_float2(U[nb][2] * eB, U[nb][3] * eB);
        }
    }
}

// ---------------- launch -----------------------------------------------------
extern "C" void kernel_launch(void* const* d_in, const int* in_sizes, int n_in,
                              void* d_out, int out_size) {
    const float* x   = (const float*)d_in[0];
    const float* mem = (const float*)d_in[1];
    float* out       = (float*)d_out;
    const int B = in_sizes[0] / DDIM;
    const int K = in_sizes[1] / DDIM;

    cudaFuncSetAttribute(memread_mma_kernel,
                         cudaFuncAttributeMaxDynamicSharedMemorySize, SM_TOTAL);

    prep_kernel<<<(MAXK * 64 + 255) / 256, 256>>>(mem, K);

    const int grid = (B + TM - 1) / TM;
    memread_mma_kernel<<<grid, 256, SM_TOTAL>>>(x, out, B, K);
}

// round 11
// speedup vs baseline: 1.1032x; 1.1032x over previous
#include <cuda_runtime.h>
#include <cuda_bf16.h>
#include <cuda_fp16.h>
#include <cstdint>

#define DDIM 50
#define MAXK 2048
#define TM   256      // rows per CTA (32 rows per warp, 8 warps)
#define TKT  64       // K-slots per tile

// ---------------- static device scratch (pre-split M) ------------------------
__device__ __align__(16) __nv_bfloat16 gMkA[MAXK * 64];   // [slot][d] hi (GEMM1)
__device__ __align__(16) __nv_bfloat16 gMkB[MAXK * 64];   // [slot][d] lo (GEMM1)
__device__ __align__(16) __half       gMdF[64 * MAXK];    // [d][slot] fp16 (GEMM2)
__device__ __align__(16) float        gMt[MAXK * 2];      // [slot][2]: m48, m49 fp32

// ---------------- smem layout (bytes) ----------------------------------------
#define ARR      9216                    // 64 rows * 144B pitch
#define SM_KH    0
#define SM_KL    ARR
#define SM_DF    (2 * ARR)
#define SM_TAIL  (3 * ARR)               // 27648
#define SM_STASH (SM_TAIL + 512)         // 28160
#define SM_TOTAL (SM_STASH + 12 * 4096)  // + 49152 = 77312

// ---------------- helpers ----------------------------------------------------
__device__ __forceinline__ uint32_t smem_u32(const void* p) {
    uint32_t a;
    asm("{ .reg .u64 t; cvta.to.shared.u64 t, %1; cvt.u32.u64 %0, t; }" : "=r"(a) : "l"(p));
    return a;
}
__device__ __forceinline__ void sts128(uint32_t addr, const uint32_t* v) {
    asm volatile("st.shared.v4.b32 [%0], {%1, %2, %3, %4};"
                 :: "r"(addr), "r"(v[0]), "r"(v[1]), "r"(v[2]), "r"(v[3]) : "memory");
}
__device__ __forceinline__ void lds128(uint32_t* v, uint32_t addr) {
    asm("ld.shared.v4.u32 {%0, %1, %2, %3}, [%4];"
        : "=r"(v[0]), "=r"(v[1]), "=r"(v[2]), "=r"(v[3]) : "r"(addr));
}
__device__ __forceinline__ float4 lds128f(uint32_t addr) {
    float4 v;
    asm("ld.shared.v4.f32 {%0, %1, %2, %3}, [%4];"
        : "=f"(v.x), "=f"(v.y), "=f"(v.z), "=f"(v.w) : "r"(addr));
    return v;
}
__device__ __forceinline__ void ldm4(uint32_t* r, uint32_t addr) {
    asm volatile("ldmatrix.sync.aligned.m8n8.x4.shared.b16 {%0,%1,%2,%3}, [%4];"
                 : "=r"(r[0]), "=r"(r[1]), "=r"(r[2]), "=r"(r[3]) : "r"(addr));
}
__device__ __forceinline__ void ldm2(uint32_t* r, uint32_t addr) {
    asm volatile("ldmatrix.sync.aligned.m8n8.x2.shared.b16 {%0,%1}, [%2];"
                 : "=r"(r[0]), "=r"(r[1]) : "r"(addr));
}
__device__ __forceinline__ uint32_t pack2(float lo, float hi) {   // -> bf16x2
    uint32_t r;
    asm("{ .reg .b16 l, h; cvt.rn.bf16.f32 l, %1; cvt.rn.bf16.f32 h, %2; mov.b32 %0, {l, h}; }"
        : "=r"(r) : "f"(lo), "f"(hi));
    return r;
}
__device__ __forceinline__ uint32_t packh2(float lo, float hi) {  // -> f16x2
    uint32_t r;
    asm("{ .reg .b16 l, h; cvt.rn.f16.f32 l, %1; cvt.rn.f16.f32 h, %2; mov.b32 %0, {l, h}; }"
        : "=r"(r) : "f"(lo), "f"(hi));
    return r;
}
__device__ __forceinline__ float bf16_rt(float v) {               // round-trip
    float r;
    asm("{ .reg .b16 t; cvt.rn.bf16.f32 t, %1; cvt.f32.bf16 %0, t; }" : "=f"(r) : "f"(v));
    return r;
}
// D += A * B   (m16n8k16, row.col, bf16 in, f32 accum)
__device__ __forceinline__ void mma(float* d, const uint32_t* a, uint32_t b0, uint32_t b1) {
    asm volatile(
        "mma.sync.aligned.m16n8k16.row.col.f32.bf16.bf16.f32 "
        "{%0,%1,%2,%3}, {%4,%5,%6,%7}, {%8,%9}, {%0,%1,%2,%3};"
        : "+f"(d[0]), "+f"(d[1]), "+f"(d[2]), "+f"(d[3])
        : "r"(a[0]), "r"(a[1]), "r"(a[2]), "r"(a[3]), "r"(b0), "r"(b1));
}
// D += A * B   (m16n8k16, row.col, fp16 in, f32 accum)
__device__ __forceinline__ void mmah(float* d, const uint32_t* a, uint32_t b0, uint32_t b1) {
    asm volatile(
        "mma.sync.aligned.m16n8k16.row.col.f32.f16.f16.f32 "
        "{%0,%1,%2,%3}, {%4,%5,%6,%7}, {%8,%9}, {%0,%1,%2,%3};"
        : "+f"(d[0]), "+f"(d[1]), "+f"(d[2]), "+f"(d[3])
        : "r"(a[0]), "r"(a[1]), "r"(a[2]), "r"(a[3]), "r"(b0), "r"(b1));
}
__device__ __forceinline__ float qmax(float v) {   // max across the tg-quad
    v = fmaxf(v, __shfl_xor_sync(0xffffffffu, v, 1));
    v = fmaxf(v, __shfl_xor_sync(0xffffffffu, v, 2));
    return v;
}
#define CP16(dst, src) asm volatile("cp.async.cg.shared.global [%0], [%1], 16;" :: "r"(dst), "l"(src))
#define CPCOMMIT()     asm volatile("cp.async.commit_group;" ::: "memory")
#define CPWAIT0()      asm volatile("cp.async.wait_group 0;" ::: "memory")

// ---------------- prep: M splits + fp16 D-major + fp32 tail -------------------
__global__ void prep_kernel(const float* __restrict__ mem, int K) {
    int i = blockIdx.x * blockDim.x + threadIdx.x;
    if (i >= MAXK * 64) return;
    int k = i >> 6, d = i & 63;
    float v = (d < DDIM && k < K) ? mem[k * DDIM + d] : 0.f;
    float h = bf16_rt(v);
    gMkA[k * 64 + d] = __float2bfloat16(h);
    gMkB[k * 64 + d] = __float2bfloat16(v - h);
    gMdF[d * MAXK + k] = __float2half(v);
    if (d < 2) gMt[k * 2 + d] = (k < K) ? mem[k * DDIM + 48 + d] : 0.f;
}

// ---------------- main fused kernel ------------------------------------------
__global__ __launch_bounds__(256, 2)
void memread_mma_kernel(const float* __restrict__ x, float* __restrict__ out, int B, int K) {
    extern __shared__ char smem[];
    const uint32_t sb = smem_u32(smem);
    const int tid = threadIdx.x, wid = tid >> 5, lane = tid & 31;
    const int g = lane >> 2, tg = lane & 3;
    const int row0 = blockIdx.x * TM;

    // per-lane ldmatrix row-address offset
    const uint32_t offm = (uint32_t)((lane & 7) * 144 + ((lane >> 3) & 1) * 16
                                     + ((lane >> 4) & 1) * 1152);

    // ---- prologue A: passthrough x -> out[:, 0:50] --------------------------
    for (int w = tid; w < TM * 32; w += 256) {
        int r = w >> 5, dp = w & 31;
        int row = row0 + r;
        if (dp < 25 && row < B) {
            float2 v = *reinterpret_cast<const float2*>(x + (size_t)row * DDIM + dp * 2);
            *reinterpret_cast<float2*>(out + (size_t)row * 100 + dp * 2) = v;
        }
    }

    // ---- prologue B: gather X A-fragments (dims 0..47), split, park in stash -
    // stash slot = rb*6 + part*3 + ks  (part 0 = hi, 1 = lo)
    const uint32_t stash = sb + SM_STASH + (uint32_t)tid * 16;
    #pragma unroll
    for (int rb = 0; rb < 2; ++rb) {
        const int rA = row0 + wid * 32 + rb * 16 + g;
        const int rB = rA + 8;
        #pragma unroll
        for (int ks = 0; ks < 3; ++ks) {
            const int c0 = ks * 16 + 2 * tg;
            const int c1 = c0 + 8;
            float2 z = make_float2(0.f, 0.f);
            float2 vA0 = (rA < B) ? *reinterpret_cast<const float2*>(x + (size_t)rA * DDIM + c0) : z;
            float2 vB0 = (rB < B) ? *reinterpret_cast<const float2*>(x + (size_t)rB * DDIM + c0) : z;
            float2 vA1 = (rA < B) ? *reinterpret_cast<const float2*>(x + (size_t)rA * DDIM + c1) : z;
            float2 vB1 = (rB < B) ? *reinterpret_cast<const float2*>(x + (size_t)rB * DDIM + c1) : z;
            float hA0x = bf16_rt(vA0.x), hA0y = bf16_rt(vA0.y);
            float hB0x = bf16_rt(vB0.x), hB0y = bf16_rt(vB0.y);
            float hA1x = bf16_rt(vA1.x), hA1y = bf16_rt(vA1.y);
            float hB1x = bf16_rt(vB1.x), hB1y = bf16_rt(vB1.y);
            uint32_t hi[4], lo[4];
            hi[0] = pack2(hA0x, hA0y);
            hi[1] = pack2(hB0x, hB0y);
            hi[2] = pack2(hA1x, hA1y);
            hi[3] = pack2(hB1x, hB1y);
            lo[0] = pack2(vA0.x - hA0x, vA0.y - hA0y);
            lo[1] = pack2(vB0.x - hB0x, vB0.y - hB0y);
            lo[2] = pack2(vA1.x - hA1x, vA1.y - hA1y);
            lo[3] = pack2(vB1.x - hB1x, vB1.y - hB1y);
            sts128(stash + (uint32_t)((rb * 6 + ks) * 4096), hi);
            sts128(stash + (uint32_t)((rb * 6 + 3 + ks) * 4096), lo);
        }
    }
    // fp32 x tail (dims 48,49) for the 4 rows this thread's scores cover
    float xt[2][4];   // [dim48/49][row: A0,B0,A1,B1]
    {
        const int rws[4] = { row0 + wid * 32 + g, row0 + wid * 32 + 8 + g,
                             row0 + wid * 32 + 16 + g, row0 + wid * 32 + 24 + g };
        #pragma unroll
        for (int j = 0; j < 4; ++j) {
            float2 v = (rws[j] < B)
                ? *reinterpret_cast<const float2*>(x + (size_t)rws[j] * DDIM + 48)
                : make_float2(0.f, 0.f);
            xt[0][j] = v.x;  xt[1][j] = v.y;
        }
    }
    __syncthreads();

    float U0[7][4], U1[7][4];
    #pragma unroll
    for (int nb = 0; nb < 7; ++nb)
        #pragma unroll
        for (int q = 0; q < 4; ++q) { U0[nb][q] = 0.f; U1[nb][q] = 0.f; }

    float mA0 = -1e30f, mB0 = -1e30f, mA1 = -1e30f, mB1 = -1e30f;

    const uint32_t KH = sb + SM_KH, KL = sb + SM_KL, DF = sb + SM_DF;
    const uint32_t TAIL = sb + SM_TAIL;
    const int ntiles = (K + TKT - 1) / TKT;

    for (int t = 0; t < ntiles; ++t) {
        // ---- load tile t ----------------------------------------------------
        #pragma unroll
        for (int c = tid; c < 512; c += 256) {
            int r = c >> 3, j = c & 7;
            uint32_t doff = (uint32_t)(r * 144 + j * 16);
            const char* sKA = (const char*)(gMkA + (size_t)(t * TKT + r) * 64) + j * 16;
            const char* sKB = (const char*)(gMkB + (size_t)(t * TKT + r) * 64) + j * 16;
            const char* sDF = (const char*)(gMdF + (size_t)r * MAXK + t * TKT) + j * 16;
            CP16(KH + doff, sKA);
            CP16(KL + doff, sKB);
            CP16(DF + doff, sDF);
        }
        if (tid < 32)   // fp32 tail: 64 slots x (m48, m49) = 512B
            CP16(TAIL + (uint32_t)tid * 16, (const char*)(gMt + (size_t)t * 128) + tid * 16);
        CPCOMMIT();
        CPWAIT0();
        __syncthreads();

        // ---- 4 substeps -----------------------------------------------------
        #pragma unroll 1
        for (int s = 0; s < 4; ++s) {
            // GEMM1: 4 fused error-comp chains (9 MMAs each), shared B-frags
            float c00[4] = {0,0,0,0}, c01[4] = {0,0,0,0};
            float c10[4] = {0,0,0,0}, c11[4] = {0,0,0,0};
            const uint32_t kb = (uint32_t)(s * 2304) + offm;
            #pragma unroll
            for (int ks = 0; ks < 3; ++ks) {
                uint32_t bh[4], bl[4], Ah0[4], Al0[4], Ah1[4], Al1[4];
                ldm4(bh, KH + kb + ks * 32);
                ldm4(bl, KL + kb + ks * 32);
                lds128(Ah0, stash + (uint32_t)(ks * 4096));
                lds128(Al0, stash + (uint32_t)((3 + ks) * 4096));
                lds128(Ah1, stash + (uint32_t)((6 + ks) * 4096));
                lds128(Al1, stash + (uint32_t)((9 + ks) * 4096));
                // round-robin across the 4 chains (gap 4 between same-chain MMAs)
                mma(c00, Ah0, bh[0], bh[1]);
                mma(c01, Ah0, bh[2], bh[3]);
                mma(c10, Ah1, bh[0], bh[1]);
                mma(c11, Ah1, bh[2], bh[3]);
                mma(c00, Ah0, bl[0], bl[1]);
                mma(c01, Ah0, bl[2], bl[3]);
                mma(c10, Ah1, bl[0], bl[1]);
                mma(c11, Ah1, bl[2], bl[3]);
                mma(c00, Al0, bh[0], bh[1]);
                mma(c01, Al0, bh[2], bh[3]);
                mma(c10, Al1, bh[0], bh[1]);
                mma(c11, Al1, bh[2], bh[3]);
            }
            float S0[8], S1[8];
            #pragma unroll
            for (int q = 0; q < 4; ++q) {
                S0[q] = c00[q];  S0[4 + q] = c01[q];
                S1[q] = c10[q];  S1[4 + q] = c11[q];
            }

            // exact fp32 fixup for dims 48,49 (2 contiguous LDS.128)
            {
                uint32_t ta = TAIL + (uint32_t)(s * 128 + tg * 16);
                float4 t0 = lds128f(ta);        // slots 2tg, 2tg+1   (nb0)
                float4 t1 = lds128f(ta + 64);   // slots 8+2tg, 8+2tg+1 (nb1)
                S0[0] += xt[0][0] * t0.x + xt[1][0] * t0.y;
                S0[1] += xt[0][0] * t0.z + xt[1][0] * t0.w;
                S0[2] += xt[0][1] * t0.x + xt[1][1] * t0.y;
                S0[3] += xt[0][1] * t0.z + xt[1][1] * t0.w;
                S0[4] += xt[0][0] * t1.x + xt[1][0] * t1.y;
                S0[5] += xt[0][0] * t1.z + xt[1][0] * t1.w;
                S0[6] += xt[0][1] * t1.x + xt[1][1] * t1.y;
                S0[7] += xt[0][1] * t1.z + xt[1][1] * t1.w;
                S1[0] += xt[0][2] * t0.x + xt[1][2] * t0.y;
                S1[1] += xt[0][2] * t0.z + xt[1][2] * t0.w;
                S1[2] += xt[0][3] * t0.x + xt[1][3] * t0.y;
                S1[3] += xt[0][3] * t0.z + xt[1][3] * t0.w;
                S1[4] += xt[0][2] * t1.x + xt[1][2] * t1.y;
                S1[5] += xt[0][2] * t1.z + xt[1][2] * t1.w;
                S1[6] += xt[0][3] * t1.x + xt[1][3] * t1.y;
                S1[7] += xt[0][3] * t1.z + xt[1][3] * t1.w;
            }

            // substep row maxes
            float sA0 = qmax(fmaxf(fmaxf(S0[0], S0[1]), fmaxf(S0[4], S0[5])));
            float sB0 = qmax(fmaxf(fmaxf(S0[2], S0[3]), fmaxf(S0[6], S0[7])));
            float sA1 = qmax(fmaxf(fmaxf(S1[0], S1[1]), fmaxf(S1[4], S1[5])));
            float sB1 = qmax(fmaxf(fmaxf(S1[2], S1[3]), fmaxf(S1[6], S1[7])));

            bool up = (sA0 > mA0) | (sB0 > mB0) | (sA1 > mA1) | (sB1 > mB1);
            if (__any_sync(0xffffffffu, up)) {
                float nA0 = fmaxf(mA0, sA0), nB0 = fmaxf(mB0, sB0);
                float nA1 = fmaxf(mA1, sA1), nB1 = fmaxf(mB1, sB1);
                float cA0 = __expf(mA0 - nA0), cB0 = __expf(mB0 - nB0);
                float cA1 = __expf(mA1 - nA1), cB1 = __expf(mB1 - nB1);
                #pragma unroll
                for (int nb = 0; nb < 7; ++nb) {
                    U0[nb][0] *= cA0; U0[nb][1] *= cA0;
                    U0[nb][2] *= cB0; U0[nb][3] *= cB0;
                    U1[nb][0] *= cA1; U1[nb][1] *= cA1;
                    U1[nb][2] *= cB1; U1[nb][3] *= cB1;
                }
                mA0 = nA0; mB0 = nB0; mA1 = nA1; mB1 = nB1;
            }

            // s' = exp(S - m_row) in fp16
            uint32_t ah0[4], ah1[4];
            ah0[0] = packh2(__expf(S0[0] - mA0), __expf(S0[1] - mA0));
            ah0[1] = packh2(__expf(S0[2] - mB0), __expf(S0[3] - mB0));
            ah0[2] = packh2(__expf(S0[4] - mA0), __expf(S0[5] - mA0));
            ah0[3] = packh2(__expf(S0[6] - mB0), __expf(S0[7] - mB0));
            ah1[0] = packh2(__expf(S1[0] - mA1), __expf(S1[1] - mA1));
            ah1[1] = packh2(__expf(S1[2] - mB1), __expf(S1[3] - mB1));
            ah1[2] = packh2(__expf(S1[4] - mA1), __expf(S1[5] - mA1));
            ah1[3] = packh2(__expf(S1[6] - mB1), __expf(S1[7] - mB1));

            // GEMM2: fp16 single pass, U[32 x 56] += s' * Md
            const uint32_t db = (uint32_t)(s * 32) + offm;
            #pragma unroll
            for (int i = 0; i < 3; ++i) {
                uint32_t dh[4];
                ldm4(dh, DF + (uint32_t)(i * 2304) + db);
                mmah(U0[2 * i],     ah0, dh[0], dh[1]);
                mmah(U1[2 * i],     ah1, dh[0], dh[1]);
                mmah(U0[2 * i + 1], ah0, dh[2], dh[3]);
                mmah(U1[2 * i + 1], ah1, dh[2], dh[3]);
            }
            {   // nb = 6 (d 48..55; 50..55 zero-padded)
                uint32_t d2[2];
                ldm2(d2, DF + 6 * 1152 + db);
                mmah(U0[6], ah0, d2[0], d2[1]);
                mmah(U1[6], ah1, d2[0], d2[1]);
            }
        }
        __syncthreads();                  // done with tile buffer
    }

    // ---- writeout U * e^m -> out[:, 50:100] ---------------------------------
    const float eA0 = __expf(mA0), eB0 = __expf(mB0);
    const float eA1 = __expf(mA1), eB1 = __expf(mB1);
    #pragma unroll
    for (int rb = 0; rb < 2; ++rb) {
        const int rA = row0 + wid * 32 + rb * 16 + g;
        const int rB = rA + 8;
        float (*U)[4] = rb ? U1 : U0;
        const float eA = rb ? eA1 : eA0;
        const float eB = rb ? eB1 : eB0;
        #pragma unroll
        for (int nb = 0; nb < 7; ++nb) {
            int col = nb * 8 + tg * 2;
            if (col < DDIM) {
                if (rA < B)
                    *reinterpret_cast<float2*>(out + (size_t)rA * 100 + 50 + col) =
                        make_float2(U[nb][0] * eA, U[nb][1] * eA);
                if (rB < B)
                    *reinterpret_cast<float2*>(out + (size_t)rB * 100 + 50 + col) =
                        make_float2(U[nb][2] * eB, U[nb][3] * eB);
            }
        }
    }
}

// ---------------- launch -----------------------------------------------------
extern "C" void kernel_launch(void* const* d_in, const int* in_sizes, int n_in,
                              void* d_out, int out_size) {
    const float* x   = (const float*)d_in[0];
    const float* mem = (const float*)d_in[1];
    float* out       = (float*)d_out;
    const int B = in_sizes[0] / DDIM;
    const int K = in_sizes[1] / DDIM;

    cudaFuncSetAttribute(memread_mma_kernel,
                         cudaFuncAttributeMaxDynamicSharedMemorySize, SM_TOTAL);

    prep_kernel<<<(MAXK * 64 + 255) / 256, 256>>>(mem, K);

    const int grid = (B + TM - 1) / TM;
    memread_mma_kernel<<<grid, 256, SM_TOTAL>>>(x, out, B, K);
}

// round 12
// speedup vs baseline: 1.1911x; 1.0797x over previous
#include <cuda_runtime.h>
#include <cuda_bf16.h>
#include <cuda_fp16.h>
#include <cstdint>

#define DDIM 50
#define MAXK 2048
#define TM   256      // rows per CTA (32 rows per warp, 8 warps)
#define TKT  128      // K-slots per tile

// ---------------- static device scratch (pre-split M) ------------------------
// gMk* are PRE-SCALED by log2(e): S accumulates in log2 units, exp -> ex2.
__device__ __align__(16) __nv_bfloat16 gMkA[MAXK * 64];   // [slot][d] hi*log2e (GEMM1)
__device__ __align__(16) __nv_bfloat16 gMkB[MAXK * 64];   // [slot][d] lo*log2e (GEMM1)
__device__ __align__(16) __half       gMdF[64 * MAXK];    // [d][slot] fp16 (GEMM2, unscaled)
__device__ __align__(16) float        gMt[MAXK * 2];      // [slot][2]: m48,m49 * log2e

// ---------------- smem layout (bytes) ----------------------------------------
#define ARRK     18432                   // 128 slot-rows * 144B pitch (KH/KL)
#define ARRD     17408                   // 64 d-rows * 272B pitch (DF)
#define SM_KH    0
#define SM_KL    ARRK
#define SM_DF    (2 * ARRK)              // 36864
#define SM_TAIL  (SM_DF + ARRD)          // 54272
#define SM_STASH (SM_TAIL + 1024)        // 55296
#define SM_TOTAL (SM_STASH + 12 * 4096)  // 104448

// ---------------- helpers ----------------------------------------------------
__device__ __forceinline__ uint32_t smem_u32(const void* p) {
    uint32_t a;
    asm("{ .reg .u64 t; cvta.to.shared.u64 t, %1; cvt.u32.u64 %0, t; }" : "=r"(a) : "l"(p));
    return a;
}
__device__ __forceinline__ void sts128(uint32_t addr, const uint32_t* v) {
    asm volatile("st.shared.v4.b32 [%0], {%1, %2, %3, %4};"
                 :: "r"(addr), "r"(v[0]), "r"(v[1]), "r"(v[2]), "r"(v[3]) : "memory");
}
__device__ __forceinline__ void lds128(uint32_t* v, uint32_t addr) {
    asm("ld.shared.v4.u32 {%0, %1, %2, %3}, [%4];"
        : "=r"(v[0]), "=r"(v[1]), "=r"(v[2]), "=r"(v[3]) : "r"(addr));
}
__device__ __forceinline__ float4 lds128f(uint32_t addr) {
    float4 v;
    asm("ld.shared.v4.f32 {%0, %1, %2, %3}, [%4];"
        : "=f"(v.x), "=f"(v.y), "=f"(v.z), "=f"(v.w) : "r"(addr));
    return v;
}
__device__ __forceinline__ void ldm4(uint32_t* r, uint32_t addr) {
    asm volatile("ldmatrix.sync.aligned.m8n8.x4.shared.b16 {%0,%1,%2,%3}, [%4];"
                 : "=r"(r[0]), "=r"(r[1]), "=r"(r[2]), "=r"(r[3]) : "r"(addr));
}
__device__ __forceinline__ void ldm2(uint32_t* r, uint32_t addr) {
    asm volatile("ldmatrix.sync.aligned.m8n8.x2.shared.b16 {%0,%1}, [%2];"
                 : "=r"(r[0]), "=r"(r[1]) : "r"(addr));
}
__device__ __forceinline__ uint32_t pack2(float lo, float hi) {   // -> bf16x2
    uint32_t r;
    asm("{ .reg .b16 l, h; cvt.rn.bf16.f32 l, %1; cvt.rn.bf16.f32 h, %2; mov.b32 %0, {l, h}; }"
        : "=r"(r) : "f"(lo), "f"(hi));
    return r;
}
__device__ __forceinline__ uint32_t packh2(float lo, float hi) {  // -> f16x2
    uint32_t r;
    asm("{ .reg .b16 l, h; cvt.rn.f16.f32 l, %1; cvt.rn.f16.f32 h, %2; mov.b32 %0, {l, h}; }"
        : "=r"(r) : "f"(lo), "f"(hi));
    return r;
}
__device__ __forceinline__ float bf16_rt(float v) {               // round-trip
    float r;
    asm("{ .reg .b16 t; cvt.rn.bf16.f32 t, %1; cvt.f32.bf16 %0, t; }" : "=f"(r) : "f"(v));
    return r;
}
__device__ __forceinline__ float ex2(float v) {                   // 2^v, 1 MUFU
    float r;
    asm("ex2.approx.ftz.f32 %0, %1;" : "=f"(r) : "f"(v));
    return r;
}
// D += A * B   (m16n8k16, row.col, bf16 in, f32 accum)
__device__ __forceinline__ void mma(float* d, const uint32_t* a, uint32_t b0, uint32_t b1) {
    asm volatile(
        "mma.sync.aligned.m16n8k16.row.col.f32.bf16.bf16.f32 "
        "{%0,%1,%2,%3}, {%4,%5,%6,%7}, {%8,%9}, {%0,%1,%2,%3};"
        : "+f"(d[0]), "+f"(d[1]), "+f"(d[2]), "+f"(d[3])
        : "r"(a[0]), "r"(a[1]), "r"(a[2]), "r"(a[3]), "r"(b0), "r"(b1));
}
// D += A * B   (m16n8k16, row.col, fp16 in, f32 accum)
__device__ __forceinline__ void mmah(float* d, const uint32_t* a, uint32_t b0, uint32_t b1) {
    asm volatile(
        "mma.sync.aligned.m16n8k16.row.col.f32.f16.f16.f32 "
        "{%0,%1,%2,%3}, {%4,%5,%6,%7}, {%8,%9}, {%0,%1,%2,%3};"
        : "+f"(d[0]), "+f"(d[1]), "+f"(d[2]), "+f"(d[3])
        : "r"(a[0]), "r"(a[1]), "r"(a[2]), "r"(a[3]), "r"(b0), "r"(b1));
}
__device__ __forceinline__ float qmax(float v) {   // max across the tg-quad
    v = fmaxf(v, __shfl_xor_sync(0xffffffffu, v, 1));
    v = fmaxf(v, __shfl_xor_sync(0xffffffffu, v, 2));
    return v;
}
#define CP16(dst, src) asm volatile("cp.async.cg.shared.global [%0], [%1], 16;" :: "r"(dst), "l"(src))
#define CPCOMMIT()     asm volatile("cp.async.commit_group;" ::: "memory")
#define CPWAIT0()      asm volatile("cp.async.wait_group 0;" ::: "memory")

#define LOG2E 1.4426950408889634f

// ---------------- prep: M splits (scaled) + fp16 D-major + scaled fp32 tail ---
__global__ void prep_kernel(const float* __restrict__ mem, int K) {
    int i = blockIdx.x * blockDim.x + threadIdx.x;
    if (i >= MAXK * 64) return;
    int k = i >> 6, d = i & 63;
    float v = (d < DDIM && k < K) ? mem[k * DDIM + d] : 0.f;
    float vs = v * LOG2E;                 // scale BEFORE splitting
    float h = bf16_rt(vs);
    gMkA[k * 64 + d] = __float2bfloat16(h);
    gMkB[k * 64 + d] = __float2bfloat16(vs - h);
    gMdF[d * MAXK + k] = __float2half(v); // GEMM2 stays unscaled
    if (d < 2) gMt[k * 2 + d] = (k < K) ? mem[k * DDIM + 48 + d] * LOG2E : 0.f;
}

// ---------------- main fused kernel ------------------------------------------
__global__ __launch_bounds__(256, 2)
void memread_mma_kernel(const float* __restrict__ x, float* __restrict__ out, int B, int K) {
    extern __shared__ char smem[];
    const uint32_t sb = smem_u32(smem);
    const int tid = threadIdx.x, wid = tid >> 5, lane = tid & 31;
    const int g = lane >> 2, tg = lane & 3;
    const int row0 = blockIdx.x * TM;

    // per-lane ldmatrix row-address offsets (pitch 144 for KH/KL, 272 for DF)
    const uint32_t offm  = (uint32_t)((lane & 7) * 144 + ((lane >> 3) & 1) * 16
                                      + ((lane >> 4) & 1) * 1152);
    const uint32_t offm2 = (uint32_t)((lane & 7) * 272 + ((lane >> 3) & 1) * 16
                                      + ((lane >> 4) & 1) * 2176);

    // ---- prologue A: passthrough x -> out[:, 0:50] --------------------------
    for (int w = tid; w < TM * 32; w += 256) {
        int r = w >> 5, dp = w & 31;
        int row = row0 + r;
        if (dp < 25 && row < B) {
            float2 v = *reinterpret_cast<const float2*>(x + (size_t)row * DDIM + dp * 2);
            *reinterpret_cast<float2*>(out + (size_t)row * 100 + dp * 2) = v;
        }
    }

    // ---- prologue B: gather X A-fragments (dims 0..47), split, park in stash -
    // stash slot = rb*6 + part*3 + ks  (part 0 = hi, 1 = lo)
    const uint32_t stash = sb + SM_STASH + (uint32_t)tid * 16;
    #pragma unroll
    for (int rb = 0; rb < 2; ++rb) {
        const int rA = row0 + wid * 32 + rb * 16 + g;
        const int rB = rA + 8;
        #pragma unroll
        for (int ks = 0; ks < 3; ++ks) {
            const int c0 = ks * 16 + 2 * tg;
            const int c1 = c0 + 8;
            float2 z = make_float2(0.f, 0.f);
            float2 vA0 = (rA < B) ? *reinterpret_cast<const float2*>(x + (size_t)rA * DDIM + c0) : z;
            float2 vB0 = (rB < B) ? *reinterpret_cast<const float2*>(x + (size_t)rB * DDIM + c0) : z;
            float2 vA1 = (rA < B) ? *reinterpret_cast<const float2*>(x + (size_t)rA * DDIM + c1) : z;
            float2 vB1 = (rB < B) ? *reinterpret_cast<const float2*>(x + (size_t)rB * DDIM + c1) : z;
            float hA0x = bf16_rt(vA0.x), hA0y = bf16_rt(vA0.y);
            float hB0x = bf16_rt(vB0.x), hB0y = bf16_rt(vB0.y);
            float hA1x = bf16_rt(vA1.x), hA1y = bf16_rt(vA1.y);
            float hB1x = bf16_rt(vB1.x), hB1y = bf16_rt(vB1.y);
            uint32_t hi[4], lo[4];
            hi[0] = pack2(hA0x, hA0y);
            hi[1] = pack2(hB0x, hB0y);
            hi[2] = pack2(hA1x, hA1y);
            hi[3] = pack2(hB1x, hB1y);
            lo[0] = pack2(vA0.x - hA0x, vA0.y - hA0y);
            lo[1] = pack2(vB0.x - hB0x, vB0.y - hB0y);
            lo[2] = pack2(vA1.x - hA1x, vA1.y - hA1y);
            lo[3] = pack2(vB1.x - hB1x, vB1.y - hB1y);
            sts128(stash + (uint32_t)((rb * 6 + ks) * 4096), hi);
            sts128(stash + (uint32_t)((rb * 6 + 3 + ks) * 4096), lo);
        }
    }
    // fp32 x tail (dims 48,49) for the 4 rows this thread's scores cover
    float xt[2][4];   // [dim48/49][row: A0,B0,A1,B1]
    {
        const int rws[4] = { row0 + wid * 32 + g, row0 + wid * 32 + 8 + g,
                             row0 + wid * 32 + 16 + g, row0 + wid * 32 + 24 + g };
        #pragma unroll
        for (int j = 0; j < 4; ++j) {
            float2 v = (rws[j] < B)
                ? *reinterpret_cast<const float2*>(x + (size_t)rws[j] * DDIM + 48)
                : make_float2(0.f, 0.f);
            xt[0][j] = v.x;  xt[1][j] = v.y;
        }
    }
    __syncthreads();

    float U0[7][4], U1[7][4];
    #pragma unroll
    for (int nb = 0; nb < 7; ++nb)
        #pragma unroll
        for (int q = 0; q < 4; ++q) { U0[nb][q] = 0.f; U1[nb][q] = 0.f; }

    // flash-style running row maxes (in log2 units)
    float mA0 = -1e30f, mB0 = -1e30f, mA1 = -1e30f, mB1 = -1e30f;

    const uint32_t KH = sb + SM_KH, KL = sb + SM_KL, DF = sb + SM_DF;
    const uint32_t TAIL = sb + SM_TAIL;
    const int ntiles = (K + TKT - 1) / TKT;

    for (int t = 0; t < ntiles; ++t) {
        // ---- load tile t (KH/KL: 128 slot-rows x 128B; DF: 64 d-rows x 256B) -
        #pragma unroll
        for (int c = tid; c < 1024; c += 256) {
            int r = c >> 3, j = c & 7;
            uint32_t doffK = (uint32_t)(r * 144 + j * 16);
            const char* sKA = (const char*)(gMkA + (size_t)(t * TKT + r) * 64) + j * 16;
            const char* sKB = (const char*)(gMkB + (size_t)(t * TKT + r) * 64) + j * 16;
            CP16(KH + doffK, sKA);
            CP16(KL + doffK, sKB);
            int d = c >> 4, j2 = c & 15;
            uint32_t doffD = (uint32_t)(d * 272 + j2 * 16);
            const char* sDF = (const char*)(gMdF + (size_t)d * MAXK + t * TKT) + j2 * 16;
            CP16(DF + doffD, sDF);
        }
        if (tid < 64)   // fp32 tail: 128 slots x (m48, m49) = 1024B
            CP16(TAIL + (uint32_t)tid * 16, (const char*)(gMt + (size_t)t * 256) + tid * 16);
        CPCOMMIT();
        CPWAIT0();
        __syncthreads();

        // ---- 8 substeps -----------------------------------------------------
        #pragma unroll 1
        for (int s = 0; s < 8; ++s) {
            // GEMM1: 4 fused error-comp chains (9 MMAs each), shared B-frags
            float c00[4] = {0,0,0,0}, c01[4] = {0,0,0,0};
            float c10[4] = {0,0,0,0}, c11[4] = {0,0,0,0};
            const uint32_t kb = (uint32_t)(s * 2304) + offm;
            #pragma unroll
            for (int ks = 0; ks < 3; ++ks) {
                uint32_t bh[4], bl[4], Ah0[4], Al0[4], Ah1[4], Al1[4];
                ldm4(bh, KH + kb + ks * 32);
                ldm4(bl, KL + kb + ks * 32);
                lds128(Ah0, stash + (uint32_t)(ks * 4096));
                lds128(Al0, stash + (uint32_t)((3 + ks) * 4096));
                lds128(Ah1, stash + (uint32_t)((6 + ks) * 4096));
                lds128(Al1, stash + (uint32_t)((9 + ks) * 4096));
                mma(c00, Ah0, bh[0], bh[1]);
                mma(c01, Ah0, bh[2], bh[3]);
                mma(c10, Ah1, bh[0], bh[1]);
                mma(c11, Ah1, bh[2], bh[3]);
                mma(c00, Ah0, bl[0], bl[1]);
                mma(c01, Ah0, bl[2], bl[3]);
                mma(c10, Ah1, bl[0], bl[1]);
                mma(c11, Ah1, bl[2], bl[3]);
                mma(c00, Al0, bh[0], bh[1]);
                mma(c01, Al0, bh[2], bh[3]);
                mma(c10, Al1, bh[0], bh[1]);
                mma(c11, Al1, bh[2], bh[3]);
            }
            float S0[8], S1[8];
            #pragma unroll
            for (int q = 0; q < 4; ++q) {
                S0[q] = c00[q];  S0[4 + q] = c01[q];
                S1[q] = c10[q];  S1[4 + q] = c11[q];
            }

            // exact fp32 fixup for dims 48,49 (scaled tail; 2 LDS.128)
            {
                uint32_t ta = TAIL + (uint32_t)(s * 128 + tg * 16);
                float4 t0 = lds128f(ta);        // slots 2tg, 2tg+1   (nb0)
                float4 t1 = lds128f(ta + 64);   // slots 8+2tg, 8+2tg+1 (nb1)
                S0[0] += xt[0][0] * t0.x + xt[1][0] * t0.y;
                S0[1] += xt[0][0] * t0.z + xt[1][0] * t0.w;
                S0[2] += xt[0][1] * t0.x + xt[1][1] * t0.y;
                S0[3] += xt[0][1] * t0.z + xt[1][1] * t0.w;
                S0[4] += xt[0][0] * t1.x + xt[1][0] * t1.y;
                S0[5] += xt[0][0] * t1.z + xt[1][0] * t1.w;
                S0[6] += xt[0][1] * t1.x + xt[1][1] * t1.y;
                S0[7] += xt[0][1] * t1.z + xt[1][1] * t1.w;
                S1[0] += xt[0][2] * t0.x + xt[1][2] * t0.y;
                S1[1] += xt[0][2] * t0.z + xt[1][2] * t0.w;
                S1[2] += xt[0][3] * t0.x + xt[1][3] * t0.y;
                S1[3] += xt[0][3] * t0.z + xt[1][3] * t0.w;
                S1[4] += xt[0][2] * t1.x + xt[1][2] * t1.y;
                S1[5] += xt[0][2] * t1.z + xt[1][2] * t1.w;
                S1[6] += xt[0][3] * t1.x + xt[1][3] * t1.y;
                S1[7] += xt[0][3] * t1.z + xt[1][3] * t1.w;
            }

            // substep row maxes
            float sA0 = qmax(fmaxf(fmaxf(S0[0], S0[1]), fmaxf(S0[4], S0[5])));
            float sB0 = qmax(fmaxf(fmaxf(S0[2], S0[3]), fmaxf(S0[6], S0[7])));
            float sA1 = qmax(fmaxf(fmaxf(S1[0], S1[1]), fmaxf(S1[4], S1[5])));
            float sB1 = qmax(fmaxf(fmaxf(S1[2], S1[3]), fmaxf(S1[6], S1[7])));

            bool up = (sA0 > mA0) | (sB0 > mB0) | (sA1 > mA1) | (sB1 > mB1);
            if (__any_sync(0xffffffffu, up)) {
                float nA0 = fmaxf(mA0, sA0), nB0 = fmaxf(mB0, sB0);
                float nA1 = fmaxf(mA1, sA1), nB1 = fmaxf(mB1, sB1);
                float cA0 = ex2(mA0 - nA0), cB0 = ex2(mB0 - nB0);
                float cA1 = ex2(mA1 - nA1), cB1 = ex2(mB1 - nB1);
                #pragma unroll
                for (int nb = 0; nb < 7; ++nb) {
                    U0[nb][0] *= cA0; U0[nb][1] *= cA0;
                    U0[nb][2] *= cB0; U0[nb][3] *= cB0;
                    U1[nb][0] *= cA1; U1[nb][1] *= cA1;
                    U1[nb][2] *= cB1; U1[nb][3] *= cB1;
                }
                mA0 = nA0; mB0 = nB0; mA1 = nA1; mB1 = nB1;
            }

            // s' = 2^(S - m_row) in fp16 (1 MUFU per value)
            uint32_t ah0[4], ah1[4];
            ah0[0] = packh2(ex2(S0[0] - mA0), ex2(S0[1] - mA0));
            ah0[1] = packh2(ex2(S0[2] - mB0), ex2(S0[3] - mB0));
            ah0[2] = packh2(ex2(S0[4] - mA0), ex2(S0[5] - mA0));
            ah0[3] = packh2(ex2(S0[6] - mB0), ex2(S0[7] - mB0));
            ah1[0] = packh2(ex2(S1[0] - mA1), ex2(S1[1] - mA1));
            ah1[1] = packh2(ex2(S1[2] - mB1), ex2(S1[3] - mB1));
            ah1[2] = packh2(ex2(S1[4] - mA1), ex2(S1[5] - mA1));
            ah1[3] = packh2(ex2(S1[6] - mB1), ex2(S1[7] - mB1));

            // GEMM2: fp16 single pass, U[32 x 56] += s' * Md
            const uint32_t db = (uint32_t)(s * 32) + offm2;
            #pragma unroll
            for (int i = 0; i < 3; ++i) {
                uint32_t dh[4];
                ldm4(dh, DF + (uint32_t)(i * 4352) + db);
                mmah(U0[2 * i],     ah0, dh[0], dh[1]);
                mmah(U1[2 * i],     ah1, dh[0], dh[1]);
                mmah(U0[2 * i + 1], ah0, dh[2], dh[3]);
                mmah(U1[2 * i + 1], ah1, dh[2], dh[3]);
            }
            {   // nb = 6 (d 48..55; 50..55 zero-padded)
                uint32_t d2[2];
                ldm2(d2, DF + 6 * 2176 + db);
                mmah(U0[6], ah0, d2[0], d2[1]);
                mmah(U1[6], ah1, d2[0], d2[1]);
            }
        }
        __syncthreads();                  // done with tile buffer
    }

    // ---- writeout U * 2^m -> out[:, 50:100] ---------------------------------
    const float eA0 = ex2(mA0), eB0 = ex2(mB0);
    const float eA1 = ex2(mA1), eB1 = ex2(mB1);
    #pragma unroll
    for (int rb = 0; rb < 2; ++rb) {
        const int rA = row0 + wid * 32 + rb * 16 + g;
        const int rB = rA + 8;
        float (*U)[4] = rb ? U1 : U0;
        const float eA = rb ? eA1 : eA0;
        const float eB = rb ? eB1 : eB0;
        #pragma unroll
        for (int nb = 0; nb < 7; ++nb) {
            int col = nb * 8 + tg * 2;
            if (col < DDIM) {
                if (rA < B)
                    *reinterpret_cast<float2*>(out + (size_t)rA * 100 + 50 + col) =
                        make_float2(U[nb][0] * eA, U[nb][1] * eA);
                if (rB < B)
                    *reinterpret_cast<float2*>(out + (size_t)rB * 100 + 50 + col) =
                        make_float2(U[nb][2] * eB, U[nb][3] * eB);
            }
        }
    }
}

// ---------------- launch -----------------------------------------------------
extern "C" void kernel_launch(void* const* d_in, const int* in_sizes, int n_in,
                              void* d_out, int out_size) {
    const float* x   = (const float*)d_in[0];
    const float* mem = (const float*)d_in[1];
    float* out       = (float*)d_out;
    const int B = in_sizes[0] / DDIM;
    const int K = in_sizes[1] / DDIM;

    cudaFuncSetAttribute(memread_mma_kernel,
                         cudaFuncAttributeMaxDynamicSharedMemorySize, SM_TOTAL);

    prep_kernel<<<(MAXK * 64 + 255) / 256, 256>>>(mem, K);

    const int grid = (B + TM - 1) / TM;
    memread_mma_kernel<<<grid, 256, SM_TOTAL>>>(x, out, B, K);
}

// round 13
// speedup vs baseline: 1.2309x; 1.0334x over previous
#include <cuda_runtime.h>
#include <cuda_bf16.h>
#include <cuda_fp16.h>
#include <cstdint>

#define DDIM 50
#define MAXK 2048
#define TM   256      // rows per CTA (32 rows per warp, 8 warps)
#define TKT  128      // K-slots per tile

// ---------------- static device scratch (pre-split M) ------------------------
// gMk* are PRE-SCALED by log2(e): S accumulates in log2 units, exp -> ex2.
__device__ __align__(16) __nv_bfloat16 gMkA[MAXK * 64];   // [slot][d] hi*log2e (GEMM1)
__device__ __align__(16) __nv_bfloat16 gMkB[MAXK * 64];   // [slot][d] lo*log2e (GEMM1)
__device__ __align__(16) __half       gMdF[64 * MAXK];    // [d][slot] fp16 (GEMM2, unscaled)
__device__ __align__(16) float        gMt[MAXK * 2];      // [slot][2]: m48,m49 * log2e

// ---------------- smem layout (bytes) ----------------------------------------
#define ARRK     18432                   // 128 slot-rows * 144B pitch (KH/KL)
#define ARRD     17408                   // 64 d-rows * 272B pitch (DF)
#define SM_KH    0
#define SM_KL    ARRK
#define SM_DF    (2 * ARRK)              // 36864
#define SM_TAIL  (SM_DF + ARRD)          // 54272
#define SM_STASH (SM_TAIL + 1024)        // 55296
#define SM_TOTAL (SM_STASH + 14 * 4096)  // + 57344 = 112640 (2 CTAs: 225.3KB <= 227KB)

// ---------------- helpers ----------------------------------------------------
__device__ __forceinline__ uint32_t smem_u32(const void* p) {
    uint32_t a;
    asm("{ .reg .u64 t; cvta.to.shared.u64 t, %1; cvt.u32.u64 %0, t; }" : "=r"(a) : "l"(p));
    return a;
}
__device__ __forceinline__ void sts128(uint32_t addr, const uint32_t* v) {
    asm volatile("st.shared.v4.b32 [%0], {%1, %2, %3, %4};"
                 :: "r"(addr), "r"(v[0]), "r"(v[1]), "r"(v[2]), "r"(v[3]) : "memory");
}
__device__ __forceinline__ void lds128(uint32_t* v, uint32_t addr) {
    asm("ld.shared.v4.u32 {%0, %1, %2, %3}, [%4];"
        : "=r"(v[0]), "=r"(v[1]), "=r"(v[2]), "=r"(v[3]) : "r"(addr));
}
__device__ __forceinline__ float4 lds128f(uint32_t addr) {
    float4 v;
    asm("ld.shared.v4.f32 {%0, %1, %2, %3}, [%4];"
        : "=f"(v.x), "=f"(v.y), "=f"(v.z), "=f"(v.w) : "r"(addr));
    return v;
}
__device__ __forceinline__ void ldm4(uint32_t* r, uint32_t addr) {
    asm volatile("ldmatrix.sync.aligned.m8n8.x4.shared.b16 {%0,%1,%2,%3}, [%4];"
                 : "=r"(r[0]), "=r"(r[1]), "=r"(r[2]), "=r"(r[3]) : "r"(addr));
}
__device__ __forceinline__ void ldm2(uint32_t* r, uint32_t addr) {
    asm volatile("ldmatrix.sync.aligned.m8n8.x2.shared.b16 {%0,%1}, [%2];"
                 : "=r"(r[0]), "=r"(r[1]) : "r"(addr));
}
// pack2(lo, hi): one-instruction f32x2 -> bf16x2 (first src = HIGH half)
__device__ __forceinline__ uint32_t pack2(float lo, float hi) {
    uint32_t r;
    asm("cvt.rn.bf16x2.f32 %0, %1, %2;" : "=r"(r) : "f"(hi), "f"(lo));
    return r;
}
// packh2(lo, hi): one-instruction f32x2 -> f16x2
__device__ __forceinline__ uint32_t packh2(float lo, float hi) {
    uint32_t r;
    asm("cvt.rn.f16x2.f32 %0, %1, %2;" : "=r"(r) : "f"(hi), "f"(lo));
    return r;
}
__device__ __forceinline__ float bf16_rt(float v) {               // round-trip
    float r;
    asm("{ .reg .b16 t; cvt.rn.bf16.f32 t, %1; cvt.f32.bf16 %0, t; }" : "=f"(r) : "f"(v));
    return r;
}
__device__ __forceinline__ float ex2(float v) {                   // 2^v, 1 MUFU
    float r;
    asm("ex2.approx.ftz.f32 %0, %1;" : "=f"(r) : "f"(v));
    return r;
}
// D += A * B   (m16n8k16, row.col, bf16 in, f32 accum)
__device__ __forceinline__ void mma(float* d, const uint32_t* a, uint32_t b0, uint32_t b1) {
    asm volatile(
        "mma.sync.aligned.m16n8k16.row.col.f32.bf16.bf16.f32 "
        "{%0,%1,%2,%3}, {%4,%5,%6,%7}, {%8,%9}, {%0,%1,%2,%3};"
        : "+f"(d[0]), "+f"(d[1]), "+f"(d[2]), "+f"(d[3])
        : "r"(a[0]), "r"(a[1]), "r"(a[2]), "r"(a[3]), "r"(b0), "r"(b1));
}
// D += A * B   (m16n8k16, row.col, fp16 in, f32 accum)
__device__ __forceinline__ void mmah(float* d, const uint32_t* a, uint32_t b0, uint32_t b1) {
    asm volatile(
        "mma.sync.aligned.m16n8k16.row.col.f32.f16.f16.f32 "
        "{%0,%1,%2,%3}, {%4,%5,%6,%7}, {%8,%9}, {%0,%1,%2,%3};"
        : "+f"(d[0]), "+f"(d[1]), "+f"(d[2]), "+f"(d[3])
        : "r"(a[0]), "r"(a[1]), "r"(a[2]), "r"(a[3]), "r"(b0), "r"(b1));
}
__device__ __forceinline__ float qmax(float v) {   // max across the tg-quad
    v = fmaxf(v, __shfl_xor_sync(0xffffffffu, v, 1));
    v = fmaxf(v, __shfl_xor_sync(0xffffffffu, v, 2));
    return v;
}
#define CP16(dst, src) asm volatile("cp.async.cg.shared.global [%0], [%1], 16;" :: "r"(dst), "l"(src))
#define CPCOMMIT()     asm volatile("cp.async.commit_group;" ::: "memory")
#define CPWAIT0()      asm volatile("cp.async.wait_group 0;" ::: "memory")

#define LOG2E 1.4426950408889634f

// ---------------- prep: M splits (scaled) + fp16 D-major + scaled fp32 tail ---
__global__ void prep_kernel(const float* __restrict__ mem, int K) {
    int i = blockIdx.x * blockDim.x + threadIdx.x;
    if (i >= MAXK * 64) return;
    int k = i >> 6, d = i & 63;
    float v = (d < DDIM && k < K) ? mem[k * DDIM + d] : 0.f;
    float vs = v * LOG2E;                 // scale BEFORE splitting
    float h = bf16_rt(vs);
    gMkA[k * 64 + d] = __float2bfloat16(h);
    gMkB[k * 64 + d] = __float2bfloat16(vs - h);
    gMdF[d * MAXK + k] = __float2half(v); // GEMM2 stays unscaled
    if (d < 2) gMt[k * 2 + d] = (k < K) ? mem[k * DDIM + 48 + d] * LOG2E : 0.f;
}

// ---------------- main fused kernel ------------------------------------------
__global__ __launch_bounds__(256, 2)
void memread_mma_kernel(const float* __restrict__ x, float* __restrict__ out, int B, int K) {
    extern __shared__ char smem[];
    const uint32_t sb = smem_u32(smem);
    const int tid = threadIdx.x, wid = tid >> 5, lane = tid & 31;
    const int g = lane >> 2, tg = lane & 3;
    const int row0 = blockIdx.x * TM;

    // per-lane ldmatrix row-address offsets (pitch 144 for KH/KL, 272 for DF)
    const uint32_t offm  = (uint32_t)((lane & 7) * 144 + ((lane >> 3) & 1) * 16
                                      + ((lane >> 4) & 1) * 1152);
    const uint32_t offm2 = (uint32_t)((lane & 7) * 272 + ((lane >> 3) & 1) * 16
                                      + ((lane >> 4) & 1) * 2176);

    // ---- prologue A: passthrough x -> out[:, 0:50] --------------------------
    for (int w = tid; w < TM * 32; w += 256) {
        int r = w >> 5, dp = w & 31;
        int row = row0 + r;
        if (dp < 25 && row < B) {
            float2 v = *reinterpret_cast<const float2*>(x + (size_t)row * DDIM + dp * 2);
            *reinterpret_cast<float2*>(out + (size_t)row * 100 + dp * 2) = v;
        }
    }

    // ---- prologue B: gather X A-fragments (dims 0..47), split, park in stash -
    // stash slot = rb*6 + part*3 + ks  (part 0 = hi, 1 = lo); slots 12,13 = x tail
    const uint32_t stash = sb + SM_STASH + (uint32_t)tid * 16;
    #pragma unroll
    for (int rb = 0; rb < 2; ++rb) {
        const int rA = row0 + wid * 32 + rb * 16 + g;
        const int rB = rA + 8;
        #pragma unroll
        for (int ks = 0; ks < 3; ++ks) {
            const int c0 = ks * 16 + 2 * tg;
            const int c1 = c0 + 8;
            float2 z = make_float2(0.f, 0.f);
            float2 vA0 = (rA < B) ? *reinterpret_cast<const float2*>(x + (size_t)rA * DDIM + c0) : z;
            float2 vB0 = (rB < B) ? *reinterpret_cast<const float2*>(x + (size_t)rB * DDIM + c0) : z;
            float2 vA1 = (rA < B) ? *reinterpret_cast<const float2*>(x + (size_t)rA * DDIM + c1) : z;
            float2 vB1 = (rB < B) ? *reinterpret_cast<const float2*>(x + (size_t)rB * DDIM + c1) : z;
            float hA0x = bf16_rt(vA0.x), hA0y = bf16_rt(vA0.y);
            float hB0x = bf16_rt(vB0.x), hB0y = bf16_rt(vB0.y);
            float hA1x = bf16_rt(vA1.x), hA1y = bf16_rt(vA1.y);
            float hB1x = bf16_rt(vB1.x), hB1y = bf16_rt(vB1.y);
            uint32_t hi[4], lo[4];
            hi[0] = pack2(hA0x, hA0y);
            hi[1] = pack2(hB0x, hB0y);
            hi[2] = pack2(hA1x, hA1y);
            hi[3] = pack2(hB1x, hB1y);
            lo[0] = pack2(vA0.x - hA0x, vA0.y - hA0y);
            lo[1] = pack2(vB0.x - hB0x, vB0.y - hB0y);
            lo[2] = pack2(vA1.x - hA1x, vA1.y - hA1y);
            lo[3] = pack2(vB1.x - hB1x, vB1.y - hB1y);
            sts128(stash + (uint32_t)((rb * 6 + ks) * 4096), hi);
            sts128(stash + (uint32_t)((rb * 6 + 3 + ks) * 4096), lo);
        }
    }
    // fp32 x tail (dims 48,49) for the 4 rows -> stash slots 12 (rb0) / 13 (rb1)
    {
        const int rws[4] = { row0 + wid * 32 + g, row0 + wid * 32 + 8 + g,
                             row0 + wid * 32 + 16 + g, row0 + wid * 32 + 24 + g };
        float t[8];
        #pragma unroll
        for (int j = 0; j < 4; ++j) {
            float2 v = (rws[j] < B)
                ? *reinterpret_cast<const float2*>(x + (size_t)rws[j] * DDIM + 48)
                : make_float2(0.f, 0.f);
            t[2 * j] = v.x;  t[2 * j + 1] = v.y;
        }
        // slot12: {x48_A0, x49_A0, x48_B0, x49_B0}; slot13: same for rb1 rows
        sts128(stash + 12 * 4096, reinterpret_cast<const uint32_t*>(&t[0]));
        sts128(stash + 13 * 4096, reinterpret_cast<const uint32_t*>(&t[4]));
    }
    __syncthreads();

    float U0[7][4], U1[7][4];
    #pragma unroll
    for (int nb = 0; nb < 7; ++nb)
        #pragma unroll
        for (int q = 0; q < 4; ++q) { U0[nb][q] = 0.f; U1[nb][q] = 0.f; }

    // flash-style running row maxes (in log2 units, quad-uniform)
    float mA0 = -1e30f, mB0 = -1e30f, mA1 = -1e30f, mB1 = -1e30f;

    const uint32_t KH = sb + SM_KH, KL = sb + SM_KL, DF = sb + SM_DF;
    const uint32_t TAIL = sb + SM_TAIL;
    const int ntiles = (K + TKT - 1) / TKT;

    for (int t = 0; t < ntiles; ++t) {
        // ---- load tile t (KH/KL: 128 slot-rows x 128B; DF: 64 d-rows x 256B) -
        #pragma unroll
        for (int c = tid; c < 1024; c += 256) {
            int r = c >> 3, j = c & 7;
            uint32_t doffK = (uint32_t)(r * 144 + j * 16);
            const char* sKA = (const char*)(gMkA + (size_t)(t * TKT + r) * 64) + j * 16;
            const char* sKB = (const char*)(gMkB + (size_t)(t * TKT + r) * 64) + j * 16;
            CP16(KH + doffK, sKA);
            CP16(KL + doffK, sKB);
            int d = c >> 4, j2 = c & 15;
            uint32_t doffD = (uint32_t)(d * 272 + j2 * 16);
            const char* sDF = (const char*)(gMdF + (size_t)d * MAXK + t * TKT) + j2 * 16;
            CP16(DF + doffD, sDF);
        }
        if (tid < 64)   // fp32 tail: 128 slots x (m48, m49) = 1024B
            CP16(TAIL + (uint32_t)tid * 16, (const char*)(gMt + (size_t)t * 256) + tid * 16);
        CPCOMMIT();
        CPWAIT0();
        __syncthreads();

        // ---- 8 substeps -----------------------------------------------------
        #pragma unroll 1
        for (int s = 0; s < 8; ++s) {
            // GEMM1: 4 fused error-comp chains (9 MMAs each), shared B-frags
            float c00[4] = {0,0,0,0}, c01[4] = {0,0,0,0};
            float c10[4] = {0,0,0,0}, c11[4] = {0,0,0,0};
            const uint32_t kb = (uint32_t)(s * 2304) + offm;
            #pragma unroll
            for (int ks = 0; ks < 3; ++ks) {
                uint32_t bh[4], bl[4], Ah0[4], Al0[4], Ah1[4], Al1[4];
                ldm4(bh, KH + kb + ks * 32);
                ldm4(bl, KL + kb + ks * 32);
                lds128(Ah0, stash + (uint32_t)(ks * 4096));
                lds128(Al0, stash + (uint32_t)((3 + ks) * 4096));
                lds128(Ah1, stash + (uint32_t)((6 + ks) * 4096));
                lds128(Al1, stash + (uint32_t)((9 + ks) * 4096));
                mma(c00, Ah0, bh[0], bh[1]);
                mma(c01, Ah0, bh[2], bh[3]);
                mma(c10, Ah1, bh[0], bh[1]);
                mma(c11, Ah1, bh[2], bh[3]);
                mma(c00, Ah0, bl[0], bl[1]);
                mma(c01, Ah0, bl[2], bl[3]);
                mma(c10, Ah1, bl[0], bl[1]);
                mma(c11, Ah1, bl[2], bl[3]);
                mma(c00, Al0, bh[0], bh[1]);
                mma(c01, Al0, bh[2], bh[3]);
                mma(c10, Al1, bh[0], bh[1]);
                mma(c11, Al1, bh[2], bh[3]);
            }
            float S0[8], S1[8];
            #pragma unroll
            for (int q = 0; q < 4; ++q) {
                S0[q] = c00[q];  S0[4 + q] = c01[q];
                S1[q] = c10[q];  S1[4 + q] = c11[q];
            }

            // exact fp32 fixup for dims 48,49 (tail + stashed x-tail; 4 LDS.128)
            {
                uint32_t ta = TAIL + (uint32_t)(s * 128 + tg * 16);
                float4 t0 = lds128f(ta);        // m-tail slots 2tg, 2tg+1   (nb0)
                float4 t1 = lds128f(ta + 64);   // m-tail slots 8+2tg..     (nb1)
                float4 xa = lds128f(stash + 12 * 4096);  // x48A0,x49A0,x48B0,x49B0
                float4 xb = lds128f(stash + 13 * 4096);  // rb1 rows
                S0[0] += xa.x * t0.x + xa.y * t0.y;
                S0[1] += xa.x * t0.z + xa.y * t0.w;
                S0[2] += xa.z * t0.x + xa.w * t0.y;
                S0[3] += xa.z * t0.z + xa.w * t0.w;
                S0[4] += xa.x * t1.x + xa.y * t1.y;
                S0[5] += xa.x * t1.z + xa.y * t1.w;
                S0[6] += xa.z * t1.x + xa.w * t1.y;
                S0[7] += xa.z * t1.z + xa.w * t1.w;
                S1[0] += xb.x * t0.x + xb.y * t0.y;
                S1[1] += xb.x * t0.z + xb.y * t0.w;
                S1[2] += xb.z * t0.x + xb.w * t0.y;
                S1[3] += xb.z * t0.z + xb.w * t0.w;
                S1[4] += xb.x * t1.x + xb.y * t1.y;
                S1[5] += xb.x * t1.z + xb.y * t1.w;
                S1[6] += xb.z * t1.x + xb.w * t1.y;
                S1[7] += xb.z * t1.z + xb.w * t1.w;
            }

            // thread-local row maxes; shfl reduction only on the rare hit-path
            float tA0 = fmaxf(fmaxf(S0[0], S0[1]), fmaxf(S0[4], S0[5]));
            float tB0 = fmaxf(fmaxf(S0[2], S0[3]), fmaxf(S0[6], S0[7]));
            float tA1 = fmaxf(fmaxf(S1[0], S1[1]), fmaxf(S1[4], S1[5]));
            float tB1 = fmaxf(fmaxf(S1[2], S1[3]), fmaxf(S1[6], S1[7]));
            bool up = (tA0 > mA0) | (tB0 > mB0) | (tA1 > mA1) | (tB1 > mB1);
            if (__any_sync(0xffffffffu, up)) {
                float nA0 = fmaxf(mA0, qmax(tA0)), nB0 = fmaxf(mB0, qmax(tB0));
                float nA1 = fmaxf(mA1, qmax(tA1)), nB1 = fmaxf(mB1, qmax(tB1));
                float cA0 = ex2(mA0 - nA0), cB0 = ex2(mB0 - nB0);
                float cA1 = ex2(mA1 - nA1), cB1 = ex2(mB1 - nB1);
                #pragma unroll
                for (int nb = 0; nb < 7; ++nb) {
                    U0[nb][0] *= cA0; U0[nb][1] *= cA0;
                    U0[nb][2] *= cB0; U0[nb][3] *= cB0;
                    U1[nb][0] *= cA1; U1[nb][1] *= cA1;
                    U1[nb][2] *= cB1; U1[nb][3] *= cB1;
                }
                mA0 = nA0; mB0 = nB0; mA1 = nA1; mB1 = nB1;
            }

            // s' = 2^(S - m_row) in fp16 (1 MUFU + shared pack per pair)
            uint32_t ah0[4], ah1[4];
            ah0[0] = packh2(ex2(S0[0] - mA0), ex2(S0[1] - mA0));
            ah0[1] = packh2(ex2(S0[2] - mB0), ex2(S0[3] - mB0));
            ah0[2] = packh2(ex2(S0[4] - mA0), ex2(S0[5] - mA0));
            ah0[3] = packh2(ex2(S0[6] - mB0), ex2(S0[7] - mB0));
            ah1[0] = packh2(ex2(S1[0] - mA1), ex2(S1[1] - mA1));
            ah1[1] = packh2(ex2(S1[2] - mB1), ex2(S1[3] - mB1));
            ah1[2] = packh2(ex2(S1[4] - mA1), ex2(S1[5] - mA1));
            ah1[3] = packh2(ex2(S1[6] - mB1), ex2(S1[7] - mB1));

            // GEMM2: fp16 single pass, U[32 x 56] += s' * Md
            const uint32_t db = (uint32_t)(s * 32) + offm2;
            #pragma unroll
            for (int i = 0; i < 3; ++i) {
                uint32_t dh[4];
                ldm4(dh, DF + (uint32_t)(i * 4352) + db);
                mmah(U0[2 * i],     ah0, dh[0], dh[1]);
                mmah(U1[2 * i],     ah1, dh[0], dh[1]);
                mmah(U0[2 * i + 1], ah0, dh[2], dh[3]);
                mmah(U1[2 * i + 1], ah1, dh[2], dh[3]);
            }
            {   // nb = 6 (d 48..55; 50..55 zero-padded)
                uint32_t d2[2];
                ldm2(d2, DF + 6 * 2176 + db);
                mmah(U0[6], ah0, d2[0], d2[1]);
                mmah(U1[6], ah1, d2[0], d2[1]);
            }
        }
        __syncthreads();                  // done with tile buffer
    }

    // ---- writeout U * 2^m -> out[:, 50:100] ---------------------------------
    const float eA0 = ex2(mA0), eB0 = ex2(mB0);
    const float eA1 = ex2(mA1), eB1 = ex2(mB1);
    #pragma unroll
    for (int rb = 0; rb < 2; ++rb) {
        const int rA = row0 + wid * 32 + rb * 16 + g;
        const int rB = rA + 8;
        float (*U)[4] = rb ? U1 : U0;
        const float eA = rb ? eA1 : eA0;
        const float eB = rb ? eB1 : eB0;
        #pragma unroll
        for (int nb = 0; nb < 7; ++nb) {
            int col = nb * 8 + tg * 2;
            if (col < DDIM) {
                if (rA < B)
                    *reinterpret_cast<float2*>(out + (size_t)rA * 100 + 50 + col) =
                        make_float2(U[nb][0] * eA, U[nb][1] * eA);
                if (rB < B)
                    *reinterpret_cast<float2*>(out + (size_t)rB * 100 + 50 + col) =
                        make_float2(U[nb][2] * eB, U[nb][3] * eB);
            }
        }
    }
}

// ---------------- launch -----------------------------------------------------
extern "C" void kernel_launch(void* const* d_in, const int* in_sizes, int n_in,
                              void* d_out, int out_size) {
    const float* x   = (const float*)d_in[0];
    const float* mem = (const float*)d_in[1];
    float* out       = (float*)d_out;
    const int B = in_sizes[0] / DDIM;
    const int K = in_sizes[1] / DDIM;

    cudaFuncSetAttribute(memread_mma_kernel,
                         cudaFuncAttributeMaxDynamicSharedMemorySize, SM_TOTAL);

    prep_kernel<<<(MAXK * 64 + 255) / 256, 256>>>(mem, K);

    const int grid = (B + TM - 1) / TM;
    memread_mma_kernel<<<grid, 256, SM_TOTAL>>>(x, out, B, K);
}